// round 1
// baseline (speedup 1.0000x reference)
#include <cuda_runtime.h>

typedef unsigned long long ull;

#define TPB 256
#define N_HIDDEN 30
#define H 16
#define S_IN 13

// ---- packed f32x2 helpers (sm_103a; FFMA2 only reachable via PTX) ----
__device__ __forceinline__ ull pack2(float lo, float hi){
    ull r; asm("mov.b64 %0, {%1, %2};" : "=l"(r) : "f"(lo), "f"(hi)); return r;
}
__device__ __forceinline__ ull dup2(float v){
    ull r; asm("mov.b64 %0, {%1, %1};" : "=l"(r) : "f"(v)); return r;
}
__device__ __forceinline__ void unpack2(ull v, float& lo, float& hi){
    asm("mov.b64 {%0, %1}, %2;" : "=f"(lo), "=f"(hi) : "l"(v));
}
__device__ __forceinline__ ull fma2(ull a, ull b, ull c){
    ull d; asm("fma.rn.f32x2 %0, %1, %2, %3;" : "=l"(d) : "l"(a), "l"(b), "l"(c)); return d;
}

__global__ __launch_bounds__(TPB, 2)
void mlp_kernel(const float* __restrict__ x,
                const float* __restrict__ W_in,  const float* __restrict__ b_in,
                const float* __restrict__ W_h,   const float* __restrict__ b_h,
                const float* __restrict__ W_out, const float* __restrict__ b_out,
                float* __restrict__ out, int half_n)
{
    // Weights repacked as j-pair f32x2: s_w[..][k][jp] = (W[2jp][k], W[2jp+1][k])
    __shared__ ull   s_win[S_IN * 8];
    __shared__ ull   s_bin[8];
    __shared__ ull   s_wh[N_HIDDEN * H * 8];
    __shared__ ull   s_bh[N_HIDDEN * 8];
    __shared__ ull   s_wout[8];          // packed over k: (W_out[2i], W_out[2i+1])
    __shared__ float s_bout;

    const int t = threadIdx.x;

    for (int i = t; i < S_IN * 8; i += TPB){
        int k = i >> 3, jp = i & 7;
        s_win[i] = pack2(W_in[(2*jp)*S_IN + k], W_in[(2*jp+1)*S_IN + k]);
    }
    if (t < 8){
        s_bin[t]  = pack2(b_in[2*t],  b_in[2*t+1]);
        s_wout[t] = pack2(W_out[2*t], W_out[2*t+1]);
    }
    for (int i = t; i < N_HIDDEN * H * 8; i += TPB){
        int l = i >> 7; int r = i & 127; int k = r >> 3, jp = r & 7;
        const float* Wl = W_h + l * (H * H);
        s_wh[i] = pack2(Wl[(2*jp)*H + k], Wl[(2*jp+1)*H + k]);
    }
    for (int i = t; i < N_HIDDEN * 8; i += TPB){
        int l = i >> 3, jp = i & 7;
        s_bh[i] = pack2(b_h[l*H + 2*jp], b_h[l*H + 2*jp + 1]);
    }
    if (t == 0) s_bout = b_out[0];
    __syncthreads();

    const int g = blockIdx.x * TPB + t;
    if (g >= half_n) return;
    const int stride = half_n;   // total threads == half_n; samples g and g+half_n

    const float* __restrict__ xp0 = x + (size_t)g * S_IN;
    const float* __restrict__ xp1 = x + (size_t)(g + stride) * S_IN;

    float h0[H], h1[H];

    // ---------- input layer: [13] -> [16], bias folded into k==0 FMA ----------
    {
        ull a0[8], a1[8];
#pragma unroll
        for (int k = 0; k < S_IN; k++){
            ull hk0 = dup2(xp0[k]);
            ull hk1 = dup2(xp1[k]);
#pragma unroll
            for (int jp = 0; jp < 8; jp++){
                ull w = s_win[k*8 + jp];
                if (k == 0){ a0[jp] = fma2(w, hk0, s_bin[jp]); a1[jp] = fma2(w, hk1, s_bin[jp]); }
                else       { a0[jp] = fma2(w, hk0, a0[jp]);    a1[jp] = fma2(w, hk1, a1[jp]); }
            }
        }
#pragma unroll
        for (int jp = 0; jp < 8; jp++){
            float lo, hi;
            unpack2(a0[jp], lo, hi); h0[2*jp] = fmaxf(lo, 0.f); h0[2*jp+1] = fmaxf(hi, 0.f);
            unpack2(a1[jp], lo, hi); h1[2*jp] = fmaxf(lo, 0.f); h1[2*jp+1] = fmaxf(hi, 0.f);
        }
    }

    // ---------- 30 hidden layers (rolled loop; body fits I$) ----------
    const ull* wl = s_wh;
    const ull* bl = s_bh;
    for (int l = 0; l < N_HIDDEN; l++){
        ull a0[8], a1[8];
#pragma unroll
        for (int k = 0; k < H; k++){
            ull hk0 = dup2(h0[k]);
            ull hk1 = dup2(h1[k]);
            const ull* wk = wl + k*8;
#pragma unroll
            for (int jp = 0; jp < 8; jp++){
                ull w = wk[jp];
                if (k == 0){ a0[jp] = fma2(w, hk0, bl[jp]);  a1[jp] = fma2(w, hk1, bl[jp]); }
                else       { a0[jp] = fma2(w, hk0, a0[jp]);  a1[jp] = fma2(w, hk1, a1[jp]); }
            }
        }
#pragma unroll
        for (int jp = 0; jp < 8; jp++){
            float lo, hi;
            unpack2(a0[jp], lo, hi); h0[2*jp] = fmaxf(lo, 0.f); h0[2*jp+1] = fmaxf(hi, 0.f);
            unpack2(a1[jp], lo, hi); h1[2*jp] = fmaxf(lo, 0.f); h1[2*jp+1] = fmaxf(hi, 0.f);
        }
        wl += H * 8;
        bl += 8;
    }

    // ---------- output layer: dot16 + b_out ----------
    {
        ull acc0 = pack2(s_bout, 0.f);
        ull acc1 = pack2(s_bout, 0.f);
#pragma unroll
        for (int i = 0; i < 8; i++){
            ull w = s_wout[i];
            acc0 = fma2(w, pack2(h0[2*i], h0[2*i+1]), acc0);
            acc1 = fma2(w, pack2(h1[2*i], h1[2*i+1]), acc1);
        }
        float lo, hi;
        unpack2(acc0, lo, hi); out[g]          = lo + hi;
        unpack2(acc1, lo, hi); out[g + stride] = lo + hi;
    }
}

extern "C" void kernel_launch(void* const* d_in, const int* in_sizes, int n_in,
                              void* d_out, int out_size)
{
    const float* x     = (const float*)d_in[0];
    const float* W_in  = (const float*)d_in[1];
    const float* b_in  = (const float*)d_in[2];
    const float* W_h   = (const float*)d_in[3];
    const float* b_h   = (const float*)d_in[4];
    const float* W_out = (const float*)d_in[5];
    const float* b_out = (const float*)d_in[6];
    float* out = (float*)d_out;

    int n = out_size;          // B
    int half = n >> 1;         // B is even (2^21); each thread handles 2 samples
    int blocks = (half + TPB - 1) / TPB;
    mlp_kernel<<<blocks, TPB>>>(x, W_in, b_in, W_h, b_h, W_out, b_out, out, half);
}

// round 2
// speedup vs baseline: 1.8184x; 1.8184x over previous
#include <cuda_runtime.h>

typedef unsigned long long ull;

#define TPB 128
#define NSAMP 4
#define N_HIDDEN 30
#define H 16
#define S_IN 13

// ---- packed f32x2 helpers (sm_103a; FFMA2 only reachable via PTX) ----
__device__ __forceinline__ ull pack2(float lo, float hi){
    ull r; asm("mov.b64 %0, {%1, %2};" : "=l"(r) : "f"(lo), "f"(hi)); return r;
}
__device__ __forceinline__ ull dup2(float v){
    ull r; asm("mov.b64 %0, {%1, %1};" : "=l"(r) : "f"(v)); return r;
}
__device__ __forceinline__ void unpack2(ull v, float& lo, float& hi){
    asm("mov.b64 {%0, %1}, %2;" : "=f"(lo), "=f"(hi) : "l"(v));
}
__device__ __forceinline__ ull fma2(ull a, ull b, ull c){
    ull d; asm("fma.rn.f32x2 %0, %1, %2, %3;" : "=l"(d) : "l"(a), "l"(b), "l"(c)); return d;
}

__global__ __launch_bounds__(TPB, 3)
void mlp_kernel(const float* __restrict__ x,
                const float* __restrict__ W_in,  const float* __restrict__ b_in,
                const float* __restrict__ W_h,   const float* __restrict__ b_h,
                const float* __restrict__ W_out, const float* __restrict__ b_out,
                float* __restrict__ out, int quarter)
{
    // Weights repacked as j-pair f32x2: s_wh[l][k][jp] = (W[2jp][k], W[2jp+1][k])
    __shared__ __align__(16) ull   s_win[S_IN * 8];
    __shared__ __align__(16) ull   s_bin[8];
    __shared__ __align__(16) ull   s_wh[N_HIDDEN * H * 8];
    __shared__ __align__(16) ull   s_bh[N_HIDDEN * 8];
    __shared__ __align__(16) ull   s_wout[8];
    __shared__ float s_bout;

    const int t = threadIdx.x;

    for (int i = t; i < S_IN * 8; i += TPB){
        int k = i >> 3, jp = i & 7;
        s_win[i] = pack2(W_in[(2*jp)*S_IN + k], W_in[(2*jp+1)*S_IN + k]);
    }
    if (t < 8){
        s_bin[t]  = pack2(b_in[2*t],  b_in[2*t+1]);
        s_wout[t] = pack2(W_out[2*t], W_out[2*t+1]);
    }
    for (int i = t; i < N_HIDDEN * H * 8; i += TPB){
        int l = i >> 7; int r = i & 127; int k = r >> 3, jp = r & 7;
        const float* Wl = W_h + l * (H * H);
        s_wh[i] = pack2(Wl[(2*jp)*H + k], Wl[(2*jp+1)*H + k]);
    }
    for (int i = t; i < N_HIDDEN * 8; i += TPB){
        int l = i >> 3, jp = i & 7;
        s_bh[i] = pack2(b_h[l*H + 2*jp], b_h[l*H + 2*jp + 1]);
    }
    if (t == 0) s_bout = b_out[0];
    __syncthreads();

    const int g = blockIdx.x * TPB + t;
    if (g >= quarter) return;
    const int Q = quarter;   // samples: g, g+Q, g+2Q, g+3Q  (coalesced stores)

    float h[NSAMP][H];

    // ---------- input layer: [13] -> [16], bias folded into k==0 FMA ----------
    {
        ull a[NSAMP][8];
#pragma unroll
        for (int k = 0; k < S_IN; k++){
            ull hk[NSAMP];
#pragma unroll
            for (int s = 0; s < NSAMP; s++)
                hk[s] = dup2(x[(size_t)(g + s*Q) * S_IN + k]);
#pragma unroll
            for (int jp = 0; jp < 8; jp++){
                ull w = s_win[k*8 + jp];
#pragma unroll
                for (int s = 0; s < NSAMP; s++)
                    a[s][jp] = fma2(w, hk[s], (k == 0) ? s_bin[jp] : a[s][jp]);
            }
        }
#pragma unroll
        for (int s = 0; s < NSAMP; s++)
#pragma unroll
            for (int jp = 0; jp < 8; jp++){
                float lo, hi; unpack2(a[s][jp], lo, hi);
                h[s][2*jp]   = fmaxf(lo, 0.f);
                h[s][2*jp+1] = fmaxf(hi, 0.f);
            }
    }

    // ---------- 30 hidden layers (rolled loop) ----------
    const ull* wl = s_wh;
    const ull* bl = s_bh;
    for (int l = 0; l < N_HIDDEN; l++){
        ull a[NSAMP][8];
#pragma unroll
        for (int k = 0; k < H; k++){
            ull hk[NSAMP];
#pragma unroll
            for (int s = 0; s < NSAMP; s++) hk[s] = dup2(h[s][k]);

            // 4x LDS.128: two weight-pairs per load
            const ulonglong2* wk = reinterpret_cast<const ulonglong2*>(wl + k*8);
            ulonglong2 w01 = wk[0], w23 = wk[1], w45 = wk[2], w67 = wk[3];
            ull w[8] = {w01.x, w01.y, w23.x, w23.y, w45.x, w45.y, w67.x, w67.y};
#pragma unroll
            for (int jp = 0; jp < 8; jp++){
#pragma unroll
                for (int s = 0; s < NSAMP; s++)
                    a[s][jp] = fma2(w[jp], hk[s], (k == 0) ? bl[jp] : a[s][jp]);
            }
        }
#pragma unroll
        for (int s = 0; s < NSAMP; s++)
#pragma unroll
            for (int jp = 0; jp < 8; jp++){
                float lo, hi; unpack2(a[s][jp], lo, hi);
                h[s][2*jp]   = fmaxf(lo, 0.f);
                h[s][2*jp+1] = fmaxf(hi, 0.f);
            }
        wl += H * 8;
        bl += 8;
    }

    // ---------- output layer: dot16 + b_out ----------
#pragma unroll
    for (int s = 0; s < NSAMP; s++){
        ull acc = pack2(s_bout, 0.f);
#pragma unroll
        for (int i = 0; i < 8; i++)
            acc = fma2(s_wout[i], pack2(h[s][2*i], h[s][2*i+1]), acc);
        float lo, hi; unpack2(acc, lo, hi);
        out[g + s*Q] = lo + hi;
    }
}

extern "C" void kernel_launch(void* const* d_in, const int* in_sizes, int n_in,
                              void* d_out, int out_size)
{
    const float* x     = (const float*)d_in[0];
    const float* W_in  = (const float*)d_in[1];
    const float* b_in  = (const float*)d_in[2];
    const float* W_h   = (const float*)d_in[3];
    const float* b_h   = (const float*)d_in[4];
    const float* W_out = (const float*)d_in[5];
    const float* b_out = (const float*)d_in[6];
    float* out = (float*)d_out;

    int n = out_size;             // B = 2^21
    int quarter = n >> 2;         // each thread handles 4 samples
    int blocks = (quarter + TPB - 1) / TPB;
    mlp_kernel<<<blocks, TPB>>>(x, W_in, b_in, W_h, b_h, W_out, b_out, out, quarter);
}